// round 1
// baseline (speedup 1.0000x reference)
#include <cuda_runtime.h>
#include <math.h>

#define Hd 512
#define Bd 4
#define Td 512
#define Ud 128
#define Vd 41
#define NP 21   // f32x2 output pairs (covers 42 cols, last .y unused)
#define KC 128  // k-chunk for Wl smem staging

// scratch (static device allocs are allowed)
__device__ float g_h1[Bd * Ud * Hd];          // gelu(tgt@W1+b1)
__device__ float g_tln[Bd * Hd * Ud];         // layernormed target, TRANSPOSED [b][k][u]

// ---------- packed f32x2 helpers ----------
__device__ __forceinline__ unsigned long long pack2(float x, float y) {
    unsigned long long r;
    asm("mov.b64 %0, {%1, %2};" : "=l"(r) : "f"(x), "f"(y));
    return r;
}
__device__ __forceinline__ void unpack2(unsigned long long v, float& x, float& y) {
    asm("mov.b64 {%0, %1}, %2;" : "=f"(x), "=f"(y) : "l"(v));
}
__device__ __forceinline__ unsigned long long fma2(unsigned long long a,
                                                   unsigned long long b,
                                                   unsigned long long c) {
    unsigned long long d;
    asm("fma.rn.f32x2 %0, %1, %2, %3;" : "=l"(d) : "l"(a), "l"(b), "l"(c));
    return d;
}

// =====================================================================
// Kernel 1a: h1 = gelu(tgt @ W1 + b1)    [512 rows x 512 cols]
// block = 8 rows x 512 cols, 256 threads (thread: 8 rows x 2 cols)
// =====================================================================
__global__ __launch_bounds__(256) void k_gemm1(const float* __restrict__ tgt,
                                               const float* __restrict__ W1,
                                               const float* __restrict__ b1) {
    __shared__ unsigned long long As2[8][Hd];   // A values duplicated into both f32x2 lanes (32KB)
    const int m0 = blockIdx.x * 8;
    const int tid = threadIdx.x;

    for (int i = tid; i < 8 * Hd; i += 256) {
        float v = tgt[m0 * Hd + i];
        ((unsigned long long*)As2)[i] = pack2(v, v);
    }
    __syncthreads();

    const int j0 = tid * 2;
    unsigned long long acc[8];
    {
        unsigned long long bb = pack2(b1[j0], b1[j0 + 1]);
#pragma unroll
        for (int r = 0; r < 8; r++) acc[r] = bb;
    }

    for (int k = 0; k < Hd; k += 4) {
        unsigned long long w[4];
#pragma unroll
        for (int q = 0; q < 4; q++) {
            float2 wv = *(const float2*)(W1 + (k + q) * Hd + j0);
            w[q] = pack2(wv.x, wv.y);
        }
#pragma unroll
        for (int q = 0; q < 4; q++) {
#pragma unroll
            for (int r = 0; r < 8; r++) acc[r] = fma2(As2[r][k + q], w[q], acc[r]);
        }
    }

#pragma unroll
    for (int r = 0; r < 8; r++) {
        float x, y;
        unpack2(acc[r], x, y);
        float gx = 0.5f * x * (1.0f + erff(x * 0.7071067811865475f));
        float gy = 0.5f * y * (1.0f + erff(y * 0.7071067811865475f));
        *(float2*)(g_h1 + (m0 + r) * Hd + j0) = make_float2(gx, gy);
    }
}

// =====================================================================
// Kernel 1b: h2 = h1 @ W2 + b2; layernorm rows; store TRANSPOSED [b][k][u]
// =====================================================================
__global__ __launch_bounds__(256) void k_gemm2_ln(const float* __restrict__ W2,
                                                  const float* __restrict__ b2,
                                                  const float* __restrict__ lng,
                                                  const float* __restrict__ lnb) {
    __shared__ unsigned long long As2[8][Hd];
    __shared__ float redS[8][8], redQ[8][8];
    __shared__ float mu_s[8], rs_s[8];
    const int m0 = blockIdx.x * 8;
    const int tid = threadIdx.x;
    const int w = tid >> 5, lane = tid & 31;

    for (int i = tid; i < 8 * Hd; i += 256) {
        float v = g_h1[m0 * Hd + i];
        ((unsigned long long*)As2)[i] = pack2(v, v);
    }
    __syncthreads();

    const int j0 = tid * 2;
    unsigned long long acc[8];
    {
        unsigned long long bb = pack2(b2[j0], b2[j0 + 1]);
#pragma unroll
        for (int r = 0; r < 8; r++) acc[r] = bb;
    }

    for (int k = 0; k < Hd; k += 4) {
        unsigned long long wv4[4];
#pragma unroll
        for (int q = 0; q < 4; q++) {
            float2 wv = *(const float2*)(W2 + (k + q) * Hd + j0);
            wv4[q] = pack2(wv.x, wv.y);
        }
#pragma unroll
        for (int q = 0; q < 4; q++) {
#pragma unroll
            for (int r = 0; r < 8; r++) acc[r] = fma2(As2[r][k + q], wv4[q], acc[r]);
        }
    }

    float xs[8], ys[8];
#pragma unroll
    for (int r = 0; r < 8; r++) unpack2(acc[r], xs[r], ys[r]);

    // per-row mean / sumsq reduction (each thread holds 2 cols of every row)
#pragma unroll
    for (int r = 0; r < 8; r++) {
        float s = xs[r] + ys[r];
        float q = xs[r] * xs[r] + ys[r] * ys[r];
#pragma unroll
        for (int off = 16; off > 0; off >>= 1) {
            s += __shfl_down_sync(0xFFFFFFFFu, s, off);
            q += __shfl_down_sync(0xFFFFFFFFu, q, off);
        }
        if (lane == 0) { redS[r][w] = s; redQ[r][w] = q; }
    }
    __syncthreads();
    if (tid < 8) {
        float s = 0.f, q = 0.f;
#pragma unroll
        for (int j = 0; j < 8; j++) { s += redS[tid][j]; q += redQ[tid][j]; }
        float mu = s * (1.0f / Hd);
        float var = q * (1.0f / Hd) - mu * mu;
        mu_s[tid] = mu;
        rs_s[tid] = rsqrtf(var + 1e-5f);
    }
    __syncthreads();

    const float gx = lng[j0], gy = lng[j0 + 1];
    const float bx = lnb[j0], by = lnb[j0 + 1];
#pragma unroll
    for (int r = 0; r < 8; r++) {
        int m = m0 + r;
        int bb = m >> 7;       // /128
        int u = m & 127;
        float ox = (xs[r] - mu_s[r]) * rs_s[r] * gx + bx;
        float oy = (ys[r] - mu_s[r]) * rs_s[r] * gy + by;
        g_tln[(bb * Hd + j0) * Ud + u] = ox;
        g_tln[(bb * Hd + j0 + 1) * Ud + u] = oy;
    }
}

// =====================================================================
// Kernel 2: out[b,t,u,:] = tanh(src[b,t,:] + tln[b,u,:]) @ Wl + bl
// block = 2 t-values x 128 u, 256 threads; thread = one (t,u) row, 41 outputs
// =====================================================================
__global__ __launch_bounds__(256) void k_joint(const float* __restrict__ src,
                                               const float* __restrict__ Wl,
                                               const float* __restrict__ bl,
                                               float* __restrict__ out) {
    __shared__ __align__(16) union {
        struct {
            float srcrow[2][Hd];                    // 4 KB
            unsigned long long wl2[KC][NP];         // 21 KB
        } c;
        float stage[8][32 * Vd];                    // 41984 B
    } sm;

    const int tid = threadIdx.x;
    const int w = tid >> 5, lane = tid & 31;
    const int tloc = w >> 2;                 // 0..1
    const int u = ((w & 3) << 5) | lane;     // 0..127
    const int bt0 = blockIdx.x * 2;          // flat b*T + t
    const int b = bt0 >> 9;                  // /512

    // load the 2 source rows (persist across k-chunks)
    for (int i = tid; i < 2 * Hd / 4; i += 256)
        ((float4*)sm.c.srcrow)[i] = ((const float4*)(src + bt0 * Hd))[i];

    unsigned long long acc[NP];
#pragma unroll
    for (int p = 0; p < NP; p++) {
        float b0v = bl[2 * p];
        float b1v = (2 * p + 1 < Vd) ? bl[2 * p + 1] : 0.f;
        acc[p] = pack2(b0v, b1v);
    }

    const float* tlp = g_tln + b * Hd * Ud + u;   // + k*Ud per k

    for (int kc = 0; kc < Hd; kc += KC) {
        __syncthreads();
        // stage Wl[kc..kc+KC) as packed pairs
        for (int i = tid; i < KC * NP; i += 256) {
            int k = i / NP, p = i % NP;
            int col = 2 * p;
            float x = Wl[(kc + k) * Vd + col];
            float y = (col + 1 < Vd) ? Wl[(kc + k) * Vd + col + 1] : 0.f;
            sm.c.wl2[k][p] = pack2(x, y);
        }
        __syncthreads();

#pragma unroll 4
        for (int k = 0; k < KC; k++) {
            float tl = tlp[(kc + k) * Ud];                  // coalesced LDG (L2-resident)
            float x = sm.c.srcrow[tloc][kc + k] + tl;       // broadcast LDS
            // tanh(x) = 1 - 2/(e^{2x}+1)  (ex2.approx + rcp.approx, rel err ~1e-6)
            float e = __expf(x + x);
            float a = 1.0f - __fdividef(2.0f, e + 1.0f);
            unsigned long long a2 = pack2(a, a);
#pragma unroll
            for (int p = 0; p < NP; p++) acc[p] = fma2(a2, sm.c.wl2[k][p], acc[p]);
        }
    }

    __syncthreads();   // release union for staging

    // stage 32x41 warp tile, then coalesced STG.128
    float* st = sm.stage[w];
#pragma unroll
    for (int p = 0; p < NP; p++) {
        float x, y;
        unpack2(acc[p], x, y);
        st[lane * Vd + 2 * p] = x;
        if (2 * p + 1 < Vd) st[lane * Vd + 2 * p + 1] = y;
    }
    __syncwarp();

    float* gdst = out + (size_t)(bt0 + tloc) * (Ud * Vd) + (w & 3) * 32 * Vd;
    const float4* st4 = (const float4*)st;
    float4* g4 = (float4*)gdst;
    for (int i = lane; i < (32 * Vd) / 4; i += 32) g4[i] = st4[i];
}

// passthrough of the two length vectors (as float, appended after main output)
__global__ void k_tail(const int* __restrict__ sl, const int* __restrict__ tl,
                       float* __restrict__ out, long long base, int count) {
    int i = threadIdx.x;
    if (i < 4 && i < count) out[base + i] = (float)sl[i];
    else if (i >= 4 && i < 8 && i < count) out[base + i] = (float)tl[i - 4];
}

extern "C" void kernel_launch(void* const* d_in, const int* in_sizes, int n_in,
                              void* d_out, int out_size) {
    const float* src = (const float*)d_in[0];
    const int*   slen = (const int*)d_in[1];
    const float* tgt = (const float*)d_in[2];
    const int*   tlen = (const int*)d_in[3];
    const float* W1 = (const float*)d_in[4];
    const float* b1 = (const float*)d_in[5];
    const float* W2 = (const float*)d_in[6];
    const float* b2 = (const float*)d_in[7];
    const float* lng = (const float*)d_in[8];
    const float* lnb = (const float*)d_in[9];
    const float* Wl = (const float*)d_in[10];
    const float* bl = (const float*)d_in[11];
    float* out = (float*)d_out;

    k_gemm1<<<Bd * Ud / 8, 256>>>(tgt, W1, b1);
    k_gemm2_ln<<<Bd * Ud / 8, 256>>>(W2, b2, lng, lnb);
    k_joint<<<Bd * Td / 2, 256>>>(src, Wl, bl, out);

    const long long MAIN = (long long)Bd * Td * Ud * Vd;   // 10,747,904
    if ((long long)out_size > MAIN) {
        int extra = (int)((long long)out_size - MAIN);
        if (extra > 8) extra = 8;
        k_tail<<<1, 8>>>(slen, tlen, out, MAIN, extra);
    }
}

// round 3
// speedup vs baseline: 2.7966x; 2.7966x over previous
#include <cuda_runtime.h>
#include <cuda_fp16.h>
#include <cstdint>
#include <math.h>

#define Hd 512
#define Bd 4
#define Td 512
#define Ud 128
#define Vd 41
#define NTILES (Bd * Td)

// ---------------- scratch ----------------
__device__ float g_h1[Bd * Ud * Hd];                         // gelu(tgt@W1+b1)
__device__ __align__(256) __half g_tlnh[Bd * Ud * Hd];       // LN target fp16, [b][kc(32)][u(128)][perm16]
__device__ __align__(256) uint32_t g_Bfrag[32 * 32 * 6 * 2]; // Wl fp16 B-fragments [kc][lane][nf][r]

// ---------------- helpers ----------------
__device__ __forceinline__ uint32_t smem_u32(const void* p) {
    uint32_t a;
    asm("{ .reg .u64 t; cvta.to.shared.u64 t, %1; cvt.u32.u64 %0, t; }" : "=r"(a) : "l"(p));
    return a;
}
__device__ __forceinline__ float2 h2f(uint32_t v) {
    __half2 h = *reinterpret_cast<__half2*>(&v);
    return __half22float2(h);
}
__device__ __forceinline__ uint32_t f2h(float x, float y) {
    __half2 h = __floats2half2_rn(x, y);
    return *reinterpret_cast<uint32_t*>(&h);
}
__device__ __forceinline__ float tanhfast(float x) {
    asm("tanh.approx.f32 %0, %0;" : "+f"(x));
    return x;
}
__device__ __forceinline__ void mma16816(float* c, uint32_t a0, uint32_t a1, uint32_t a2, uint32_t a3,
                                         uint32_t b0, uint32_t b1) {
    asm volatile(
        "mma.sync.aligned.m16n8k16.row.col.f32.f16.f16.f32 "
        "{%0,%1,%2,%3}, {%4,%5,%6,%7}, {%8,%9}, {%0,%1,%2,%3};"
        : "+f"(c[0]), "+f"(c[1]), "+f"(c[2]), "+f"(c[3])
        : "r"(a0), "r"(a1), "r"(a2), "r"(a3), "r"(b0), "r"(b1));
}

// packed f32x2 (prologue GEMMs)
__device__ __forceinline__ unsigned long long pack2(float x, float y) {
    unsigned long long r; asm("mov.b64 %0, {%1, %2};" : "=l"(r) : "f"(x), "f"(y)); return r;
}
__device__ __forceinline__ void unpack2(unsigned long long v, float& x, float& y) {
    asm("mov.b64 {%0, %1}, %2;" : "=f"(x), "=f"(y) : "l"(v));
}
__device__ __forceinline__ unsigned long long fma2(unsigned long long a, unsigned long long b, unsigned long long c) {
    unsigned long long d; asm("fma.rn.f32x2 %0, %1, %2, %3;" : "=l"(d) : "l"(a), "l"(b), "l"(c)); return d;
}

// =====================================================================
// Kernel 1a: h1 = gelu(tgt @ W1 + b1)
// =====================================================================
__global__ __launch_bounds__(256) void k_gemm1(const float* __restrict__ tgt,
                                               const float* __restrict__ W1,
                                               const float* __restrict__ b1) {
    __shared__ unsigned long long As2[8][Hd];
    const int m0 = blockIdx.x * 8;
    const int tid = threadIdx.x;

    for (int i = tid; i < 8 * Hd; i += 256) {
        float v = tgt[m0 * Hd + i];
        ((unsigned long long*)As2)[i] = pack2(v, v);
    }
    __syncthreads();

    const int j0 = tid * 2;
    unsigned long long acc[8];
    {
        unsigned long long bb = pack2(b1[j0], b1[j0 + 1]);
#pragma unroll
        for (int r = 0; r < 8; r++) acc[r] = bb;
    }
    for (int k = 0; k < Hd; k += 4) {
        unsigned long long w[4];
#pragma unroll
        for (int q = 0; q < 4; q++) {
            float2 wv = *(const float2*)(W1 + (k + q) * Hd + j0);
            w[q] = pack2(wv.x, wv.y);
        }
#pragma unroll
        for (int q = 0; q < 4; q++)
#pragma unroll
            for (int r = 0; r < 8; r++) acc[r] = fma2(As2[r][k + q], w[q], acc[r]);
    }
#pragma unroll
    for (int r = 0; r < 8; r++) {
        float x, y; unpack2(acc[r], x, y);
        float gx = 0.5f * x * (1.0f + erff(x * 0.7071067811865475f));
        float gy = 0.5f * y * (1.0f + erff(y * 0.7071067811865475f));
        *(float2*)(g_h1 + (m0 + r) * Hd + j0) = make_float2(gx, gy);
    }
}

// =====================================================================
// Kernel 1b: h2 = h1 @ W2 + b2; layernorm; store fp16 permuted for mma A-frags
// layout: g_tlnh[((b*32+kc)*128+u)*16 + tig*4 + hi*2 + lo], k = kc*16+tig*2+hi*8+lo
// =====================================================================
__global__ __launch_bounds__(256) void k_gemm2_ln(const float* __restrict__ W2,
                                                  const float* __restrict__ b2,
                                                  const float* __restrict__ lng,
                                                  const float* __restrict__ lnb) {
    __shared__ unsigned long long As2[8][Hd];
    __shared__ float redS[8][8], redQ[8][8];
    __shared__ float mu_s[8], rs_s[8];
    const int m0 = blockIdx.x * 8;
    const int tid = threadIdx.x;
    const int w = tid >> 5, lane = tid & 31;

    for (int i = tid; i < 8 * Hd; i += 256) {
        float v = g_h1[m0 * Hd + i];
        ((unsigned long long*)As2)[i] = pack2(v, v);
    }
    __syncthreads();

    const int j0 = tid * 2;
    unsigned long long acc[8];
    {
        unsigned long long bb = pack2(b2[j0], b2[j0 + 1]);
#pragma unroll
        for (int r = 0; r < 8; r++) acc[r] = bb;
    }
    for (int k = 0; k < Hd; k += 4) {
        unsigned long long wv4[4];
#pragma unroll
        for (int q = 0; q < 4; q++) {
            float2 wv = *(const float2*)(W2 + (k + q) * Hd + j0);
            wv4[q] = pack2(wv.x, wv.y);
        }
#pragma unroll
        for (int q = 0; q < 4; q++)
#pragma unroll
            for (int r = 0; r < 8; r++) acc[r] = fma2(As2[r][k + q], wv4[q], acc[r]);
    }

    float xs[8], ys[8];
#pragma unroll
    for (int r = 0; r < 8; r++) unpack2(acc[r], xs[r], ys[r]);

#pragma unroll
    for (int r = 0; r < 8; r++) {
        float s = xs[r] + ys[r];
        float q = xs[r] * xs[r] + ys[r] * ys[r];
#pragma unroll
        for (int off = 16; off > 0; off >>= 1) {
            s += __shfl_down_sync(0xFFFFFFFFu, s, off);
            q += __shfl_down_sync(0xFFFFFFFFu, q, off);
        }
        if (lane == 0) { redS[r][w] = s; redQ[r][w] = q; }
    }
    __syncthreads();
    if (tid < 8) {
        float s = 0.f, q = 0.f;
#pragma unroll
        for (int j = 0; j < 8; j++) { s += redS[tid][j]; q += redQ[tid][j]; }
        float mu = s * (1.0f / Hd);
        float var = q * (1.0f / Hd) - mu * mu;
        mu_s[tid] = mu;
        rs_s[tid] = rsqrtf(var + 1e-5f);
    }
    __syncthreads();

    const float gx = lng[j0], gy = lng[j0 + 1];
    const float bx = lnb[j0], by = lnb[j0 + 1];
    const int kc = j0 >> 4, tig = (j0 >> 1) & 3, hi = (j0 >> 3) & 1;
#pragma unroll
    for (int r = 0; r < 8; r++) {
        int m = m0 + r;
        int bb = m >> 7, u = m & 127;
        float ox = (xs[r] - mu_s[r]) * rs_s[r] * gx + bx;
        float oy = (ys[r] - mu_s[r]) * rs_s[r] * gy + by;
        __half2 hv = __floats2half2_rn(ox, oy);
        *(__half2*)(g_tlnh + (((size_t)(bb * 32 + kc) * 128 + u) * 16 + tig * 4 + hi * 2)) = hv;
    }
}

// =====================================================================
// prepB: Wl -> fp16 mma B-fragments, per-thread contiguous
// g_Bfrag[((kc*32+lane)*6+nf)*2+r] = half2(Wl[k0][n], Wl[k0+1][n]),
// k0 = kc*16 + tig*2 + r*8, n = nf*8 + gid  (zero-padded for n>=41)
// =====================================================================
__global__ void k_prepB(const float* __restrict__ Wl) {
    int idx = blockIdx.x * 256 + threadIdx.x;   // 0..12287
    if (idx >= 12288) return;
    int r = idx & 1;
    int nf = (idx >> 1) % 6;
    int rest = (idx >> 1) / 6;          // kc*32 + lane
    int lane = rest & 31, kc = rest >> 5;
    int gid = lane >> 2, tig = lane & 3;
    int n = nf * 8 + gid;
    int k0 = kc * 16 + tig * 2 + r * 8;
    float lo = (n < Vd) ? Wl[k0 * Vd + n] : 0.f;
    float hi = (n < Vd) ? Wl[(k0 + 1) * Vd + n] : 0.f;
    g_Bfrag[idx] = f2h(lo, hi);
}

// =====================================================================
// Fused: act = tanh(src_t + tln_u) -> mma.sync m16n8k16 -> out
// =====================================================================
#define SM_BS   0
#define SM_TLN  49152
#define SM_SRCP 98304
#define SM_BLS  102400
#define SM_TOT  102656

__global__ __launch_bounds__(256, 2)
void k_fused(const float* __restrict__ src, const float* __restrict__ bl,
             float* __restrict__ out) {
    extern __shared__ __align__(16) char sm[];
    const int tid = threadIdx.x, w = tid >> 5, lane = tid & 31;
    const int gid = lane >> 2, tig = lane & 3;

    // one-time: copy B fragments (48KB) + padded bias
    {
        uint4* Bs = (uint4*)(sm + SM_BS);
        const uint4* Bg = (const uint4*)g_Bfrag;
        for (int i = tid; i < 3072; i += 256) Bs[i] = Bg[i];
        float* bls = (float*)(sm + SM_BLS);
        if (tid < 48) bls[tid] = (tid < Vd) ? bl[tid] : 0.f;
    }

    const uint4* Bsv = (const uint4*)(sm + SM_BS);
    const float4* srcp4 = (const float4*)(sm + SM_SRCP);
    const float* bls = (const float*)(sm + SM_BLS);
    const int u0 = w * 16 + gid;

    for (int tile = blockIdx.x; tile < NTILES; tile += gridDim.x) {
        const int b = tile >> 9;
        __syncthreads();   // close out previous tile's smem reads

        // stage permuted source row (double buffered by tile parity)
        if (tid < 128) {
            const float* sp = src + (size_t)tile * Hd;
            int skc = tid >> 2, stg = tid & 3;
            float2 xa = *(const float2*)(sp + skc * 16 + stg * 2);
            float2 xb = *(const float2*)(sp + skc * 16 + stg * 2 + 8);
            ((float4*)(sm + SM_SRCP))[(tile & 1) * 128 + tid] = make_float4(xa.x, xa.y, xb.x, xb.y);
        }

        // prefetch tln K64-chunks 0,1 (triple-buffered cp.async)
        const char* gtb = (const char*)g_tlnh + (size_t)b * 131072;
#pragma unroll
        for (int pc = 0; pc < 2; ++pc) {
            const char* gp = gtb + pc * 16384 + tid * 64;
            uint32_t sa = smem_u32(sm + SM_TLN + pc * 16384 + tid * 64);
#pragma unroll
            for (int j = 0; j < 4; ++j)
                asm volatile("cp.async.cg.shared.global [%0], [%1], 16;"
                             :: "r"(sa + j * 16), "l"(gp + j * 16) : "memory");
            asm volatile("cp.async.commit_group;" ::: "memory");
        }

        float acc[6][4];
#pragma unroll
        for (int nf = 0; nf < 6; ++nf)
#pragma unroll
            for (int q = 0; q < 4; ++q) acc[nf][q] = 0.f;

        const int sbase = (tile & 1) * 128;

        for (int c = 0; c < 8; ++c) {
            if (c < 7) asm volatile("cp.async.wait_group 1;" ::: "memory");
            else       asm volatile("cp.async.wait_group 0;" ::: "memory");
            __syncthreads();
            if (c + 2 < 8) {
                int bi = (c + 2) % 3;
                const char* gp = gtb + (c + 2) * 16384 + tid * 64;
                uint32_t sa = smem_u32(sm + SM_TLN + bi * 16384 + tid * 64);
#pragma unroll
                for (int j = 0; j < 4; ++j)
                    asm volatile("cp.async.cg.shared.global [%0], [%1], 16;"
                                 :: "r"(sa + j * 16), "l"(gp + j * 16) : "memory");
                asm volatile("cp.async.commit_group;" ::: "memory");
            }

            const char* tb = sm + SM_TLN + (c % 3) * 16384;
#pragma unroll
            for (int sub = 0; sub < 4; ++sub) {
                const int kc = c * 4 + sub;
                const char* tsub = tb + sub * 4096;
                uint2 A0 = *(const uint2*)(tsub + u0 * 32 + tig * 8);
                uint2 A1 = *(const uint2*)(tsub + (u0 + 8) * 32 + tig * 8);
                float4 S = srcp4[sbase + kc * 4 + tig];

                float2 f0 = h2f(A0.x), f2 = h2f(A0.y);
                float2 f1 = h2f(A1.x), f3 = h2f(A1.y);
                uint32_t a0 = f2h(tanhfast(S.x + f0.x), tanhfast(S.y + f0.y));
                uint32_t a2 = f2h(tanhfast(S.z + f2.x), tanhfast(S.w + f2.y));
                uint32_t a1 = f2h(tanhfast(S.x + f1.x), tanhfast(S.y + f1.y));
                uint32_t a3 = f2h(tanhfast(S.z + f3.x), tanhfast(S.w + f3.y));

                const uint4* bp = Bsv + (kc * 32 + lane) * 3;
                uint4 B0 = bp[0], B1 = bp[1], B2 = bp[2];
                mma16816(acc[0], a0, a1, a2, a3, B0.x, B0.y);
                mma16816(acc[1], a0, a1, a2, a3, B0.z, B0.w);
                mma16816(acc[2], a0, a1, a2, a3, B1.x, B1.y);
                mma16816(acc[3], a0, a1, a2, a3, B1.z, B1.w);
                mma16816(acc[4], a0, a1, a2, a3, B2.x, B2.y);
                mma16816(acc[5], a0, a1, a2, a3, B2.z, B2.w);
            }
        }

        // epilogue: bias + scalar stores (41 cols, row stride 41 floats)
        float* orow0 = out + ((size_t)tile * 128 + u0) * Vd;
        float* orow1 = orow0 + 8 * Vd;
#pragma unroll
        for (int nf = 0; nf < 6; ++nf) {
            int n = nf * 8 + tig * 2;
            if (n < Vd) {
                float bb0 = bls[n];
                orow0[n] = acc[nf][0] + bb0;
                orow1[n] = acc[nf][2] + bb0;
            }
            if (n + 1 < Vd) {
                float bb1 = bls[n + 1];
                orow0[n + 1] = acc[nf][1] + bb1;
                orow1[n + 1] = acc[nf][3] + bb1;
            }
        }
    }
}

__global__ void k_nop() {}

__global__ void k_tail(const int* __restrict__ sl, const int* __restrict__ tl,
                       float* __restrict__ out, long long base, int count) {
    int i = threadIdx.x;
    if (i < 4 && i < count) out[base + i] = (float)sl[i];
    else if (i >= 4 && i < 8 && i < count) out[base + i] = (float)tl[i - 4];
}

extern "C" void kernel_launch(void* const* d_in, const int* in_sizes, int n_in,
                              void* d_out, int out_size) {
    const float* src = (const float*)d_in[0];
    const int*   slen = (const int*)d_in[1];
    const float* tgt = (const float*)d_in[2];
    const int*   tlen = (const int*)d_in[3];
    const float* W1 = (const float*)d_in[4];
    const float* b1 = (const float*)d_in[5];
    const float* W2 = (const float*)d_in[6];
    const float* b2 = (const float*)d_in[7];
    const float* lng = (const float*)d_in[8];
    const float* lnb = (const float*)d_in[9];
    const float* Wl = (const float*)d_in[10];
    const float* bl = (const float*)d_in[11];
    float* out = (float*)d_out;

    cudaFuncSetAttribute(k_fused, cudaFuncAttributeMaxDynamicSharedMemorySize, SM_TOT);

    k_gemm1<<<Bd * Ud / 8, 256>>>(tgt, W1, b1);
    k_prepB<<<48, 256>>>(Wl);
    k_gemm2_ln<<<Bd * Ud / 8, 256>>>(W2, b2, lng, lnb);
    k_nop<<<1, 32>>>();
    k_nop<<<1, 32>>>();                         // k_fused is launch idx 5 for ncu -s 5 -c 1
    k_fused<<<296, 256, SM_TOT>>>(src, bl, out);

    const long long MAIN = (long long)Bd * Td * Ud * Vd;   // 10,747,904
    if ((long long)out_size > MAIN) {
        int extra = (int)((long long)out_size - MAIN);
        if (extra > 8) extra = 8;
        k_tail<<<1, 8>>>(slen, tlen, out, MAIN, extra);
    }
}

// round 5
// speedup vs baseline: 3.0044x; 1.0743x over previous
#include <cuda_runtime.h>
#include <cuda_fp16.h>
#include <cstdint>
#include <math.h>

#define Hd 512
#define Bd 4
#define Td 512
#define Ud 128
#define Vd 41
#define NTILES (Bd * Td)

// ---------------- scratch ----------------
__device__ float g_h1[Bd * Ud * Hd];                         // gelu(tgt@W1+b1)
__device__ __align__(256) __half g_tlnh[Bd * Ud * Hd];       // LN target fp16, [b][kc(32)][u(128)][perm16]
__device__ __align__(256) uint32_t g_Bfrag[32 * 32 * 6 * 2]; // Wl fp16 B-fragments [kc][lane][nf][r]

// ---------------- helpers ----------------
__device__ __forceinline__ uint32_t smem_u32(const void* p) {
    uint32_t a;
    asm("{ .reg .u64 t; cvta.to.shared.u64 t, %1; cvt.u32.u64 %0, t; }" : "=r"(a) : "l"(p));
    return a;
}
__device__ __forceinline__ uint32_t f2h(float x, float y) {
    __half2 h = __floats2half2_rn(x, y);
    return *reinterpret_cast<uint32_t*>(&h);
}
__device__ __forceinline__ uint32_t hadd2u(uint32_t a, uint32_t b) {
    uint32_t d;
    asm("add.f16x2 %0, %1, %2;" : "=r"(d) : "r"(a), "r"(b));
    return d;
}
__device__ __forceinline__ uint32_t tanh2(uint32_t x) {
    asm("tanh.approx.f16x2 %0, %0;" : "+r"(x));
    return x;
}
__device__ __forceinline__ void mma16816(float* c, uint32_t a0, uint32_t a1, uint32_t a2, uint32_t a3,
                                         uint32_t b0, uint32_t b1) {
    asm volatile(
        "mma.sync.aligned.m16n8k16.row.col.f32.f16.f16.f32 "
        "{%0,%1,%2,%3}, {%4,%5,%6,%7}, {%8,%9}, {%0,%1,%2,%3};"
        : "+f"(c[0]), "+f"(c[1]), "+f"(c[2]), "+f"(c[3])
        : "r"(a0), "r"(a1), "r"(a2), "r"(a3), "r"(b0), "r"(b1));
}

// packed f32x2 (prologue GEMMs)
__device__ __forceinline__ unsigned long long pack2(float x, float y) {
    unsigned long long r; asm("mov.b64 %0, {%1, %2};" : "=l"(r) : "f"(x), "f"(y)); return r;
}
__device__ __forceinline__ void unpack2(unsigned long long v, float& x, float& y) {
    asm("mov.b64 {%0, %1}, %2;" : "=f"(x), "=f"(y) : "l"(v));
}
__device__ __forceinline__ unsigned long long fma2(unsigned long long a, unsigned long long b, unsigned long long c) {
    unsigned long long d; asm("fma.rn.f32x2 %0, %1, %2, %3;" : "=l"(d) : "l"(a), "l"(b), "l"(c)); return d;
}

// =====================================================================
// Kernel 1a: h1 = gelu(tgt @ W1 + b1)
// =====================================================================
__global__ __launch_bounds__(256) void k_gemm1(const float* __restrict__ tgt,
                                               const float* __restrict__ W1,
                                               const float* __restrict__ b1) {
    __shared__ unsigned long long As2[8][Hd];
    const int m0 = blockIdx.x * 8;
    const int tid = threadIdx.x;

    for (int i = tid; i < 8 * Hd; i += 256) {
        float v = tgt[m0 * Hd + i];
        ((unsigned long long*)As2)[i] = pack2(v, v);
    }
    __syncthreads();

    const int j0 = tid * 2;
    unsigned long long acc[8];
    {
        unsigned long long bb = pack2(b1[j0], b1[j0 + 1]);
#pragma unroll
        for (int r = 0; r < 8; r++) acc[r] = bb;
    }
    for (int k = 0; k < Hd; k += 4) {
        unsigned long long w[4];
#pragma unroll
        for (int q = 0; q < 4; q++) {
            float2 wv = *(const float2*)(W1 + (k + q) * Hd + j0);
            w[q] = pack2(wv.x, wv.y);
        }
#pragma unroll
        for (int q = 0; q < 4; q++)
#pragma unroll
            for (int r = 0; r < 8; r++) acc[r] = fma2(As2[r][k + q], w[q], acc[r]);
    }
#pragma unroll
    for (int r = 0; r < 8; r++) {
        float x, y; unpack2(acc[r], x, y);
        float gx = 0.5f * x * (1.0f + erff(x * 0.7071067811865475f));
        float gy = 0.5f * y * (1.0f + erff(y * 0.7071067811865475f));
        *(float2*)(g_h1 + (m0 + r) * Hd + j0) = make_float2(gx, gy);
    }
}

// =====================================================================
// Kernel 1b: h2 = h1 @ W2 + b2; layernorm; store fp16 permuted for mma A-frags
// layout: g_tlnh[((b*32+kc)*128+u)*16 + tig*4 + hi*2 + lo], k = kc*16+tig*2+hi*8+lo
// =====================================================================
__global__ __launch_bounds__(256) void k_gemm2_ln(const float* __restrict__ W2,
                                                  const float* __restrict__ b2,
                                                  const float* __restrict__ lng,
                                                  const float* __restrict__ lnb) {
    __shared__ unsigned long long As2[8][Hd];
    __shared__ float redS[8][8], redQ[8][8];
    __shared__ float mu_s[8], rs_s[8];
    const int m0 = blockIdx.x * 8;
    const int tid = threadIdx.x;
    const int w = tid >> 5, lane = tid & 31;

    for (int i = tid; i < 8 * Hd; i += 256) {
        float v = g_h1[m0 * Hd + i];
        ((unsigned long long*)As2)[i] = pack2(v, v);
    }
    __syncthreads();

    const int j0 = tid * 2;
    unsigned long long acc[8];
    {
        unsigned long long bb = pack2(b2[j0], b2[j0 + 1]);
#pragma unroll
        for (int r = 0; r < 8; r++) acc[r] = bb;
    }
    for (int k = 0; k < Hd; k += 4) {
        unsigned long long wv4[4];
#pragma unroll
        for (int q = 0; q < 4; q++) {
            float2 wv = *(const float2*)(W2 + (k + q) * Hd + j0);
            wv4[q] = pack2(wv.x, wv.y);
        }
#pragma unroll
        for (int q = 0; q < 4; q++)
#pragma unroll
            for (int r = 0; r < 8; r++) acc[r] = fma2(As2[r][k + q], wv4[q], acc[r]);
    }

    float xs[8], ys[8];
#pragma unroll
    for (int r = 0; r < 8; r++) unpack2(acc[r], xs[r], ys[r]);

#pragma unroll
    for (int r = 0; r < 8; r++) {
        float s = xs[r] + ys[r];
        float q = xs[r] * xs[r] + ys[r] * ys[r];
#pragma unroll
        for (int off = 16; off > 0; off >>= 1) {
            s += __shfl_down_sync(0xFFFFFFFFu, s, off);
            q += __shfl_down_sync(0xFFFFFFFFu, q, off);
        }
        if (lane == 0) { redS[r][w] = s; redQ[r][w] = q; }
    }
    __syncthreads();
    if (tid < 8) {
        float s = 0.f, q = 0.f;
#pragma unroll
        for (int j = 0; j < 8; j++) { s += redS[tid][j]; q += redQ[tid][j]; }
        float mu = s * (1.0f / Hd);
        float var = q * (1.0f / Hd) - mu * mu;
        mu_s[tid] = mu;
        rs_s[tid] = rsqrtf(var + 1e-5f);
    }
    __syncthreads();

    const float gx = lng[j0], gy = lng[j0 + 1];
    const float bx = lnb[j0], by = lnb[j0 + 1];
    const int kc = j0 >> 4, tig = (j0 >> 1) & 3, hi = (j0 >> 3) & 1;
#pragma unroll
    for (int r = 0; r < 8; r++) {
        int m = m0 + r;
        int bb = m >> 7, u = m & 127;
        float ox = (xs[r] - mu_s[r]) * rs_s[r] * gx + bx;
        float oy = (ys[r] - mu_s[r]) * rs_s[r] * gy + by;
        __half2 hv = __floats2half2_rn(ox, oy);
        *(__half2*)(g_tlnh + (((size_t)(bb * 32 + kc) * 128 + u) * 16 + tig * 4 + hi * 2)) = hv;
    }
}

// =====================================================================
// prepB: Wl -> fp16 mma B-fragments, per-thread contiguous
// =====================================================================
__global__ void k_prepB(const float* __restrict__ Wl) {
    int idx = blockIdx.x * 256 + threadIdx.x;   // 0..12287
    if (idx >= 12288) return;
    int r = idx & 1;
    int nf = (idx >> 1) % 6;
    int rest = (idx >> 1) / 6;          // kc*32 + lane
    int lane = rest & 31, kc = rest >> 5;
    int gid = lane >> 2, tig = lane & 3;
    int n = nf * 8 + gid;
    int k0 = kc * 16 + tig * 2 + r * 8;
    float lo = (n < Vd) ? Wl[k0 * Vd + n] : 0.f;
    float hi = (n < Vd) ? Wl[(k0 + 1) * Vd + n] : 0.f;
    g_Bfrag[idx] = f2h(lo, hi);
}

// =====================================================================
// Fused: act = tanh2(srch + tln) -> mma.sync m16n8k16 -> staged epilogue
// =====================================================================
#define SM_BS   0
#define SM_TLN  49152      // 3 x 16KB tln chunk buffers (also reused as 21KB epilogue stage)
#define SM_SRCP 98304      // 2 x 1KB permuted src half2 (double buffered)
#define SM_BLS  100352
#define SM_TOT  100608

__global__ __launch_bounds__(256, 2)
void k_fused(const float* __restrict__ src, const float* __restrict__ bl,
             float* __restrict__ out) {
    extern __shared__ __align__(16) char sm[];
    const int tid = threadIdx.x, w = tid >> 5, lane = tid & 31;
    const int gid = lane >> 2, tig = lane & 3;

    // one-time: copy B fragments (48KB) + padded bias
    {
        uint4* Bs = (uint4*)(sm + SM_BS);
        const uint4* Bg = (const uint4*)g_Bfrag;
        for (int i = tid; i < 3072; i += 256) Bs[i] = Bg[i];
        float* bls = (float*)(sm + SM_BLS);
        if (tid < 48) bls[tid] = (tid < Vd) ? bl[tid] : 0.f;
    }

    const uint4* Bsv = (const uint4*)(sm + SM_BS);
    const uint2* srcp2 = (const uint2*)(sm + SM_SRCP);
    const float* bls = (const float*)(sm + SM_BLS);
    const int u0 = w * 16 + gid;

    for (int tile = blockIdx.x; tile < NTILES; tile += gridDim.x) {
        const int b = tile >> 9;
        __syncthreads();   // close out previous tile's smem reads (stage + srcp)

        // stage permuted source row as half2 pairs (double buffered by tile parity)
        if (tid < 128) {
            const float* sp = src + (size_t)tile * Hd;
            int skc = tid >> 2, stg = tid & 3;
            float2 xa = *(const float2*)(sp + skc * 16 + stg * 2);
            float2 xb = *(const float2*)(sp + skc * 16 + stg * 2 + 8);
            uint2 pv;
            pv.x = f2h(xa.x, xa.y);
            pv.y = f2h(xb.x, xb.y);
            ((uint2*)(sm + SM_SRCP))[(tile & 1) * 128 + tid] = pv;
        }

        // prefetch tln K64-chunks 0,1 (triple-buffered cp.async)
        const char* gtb = (const char*)g_tlnh + (size_t)b * 131072;
#pragma unroll
        for (int pc = 0; pc < 2; ++pc) {
            const char* gp = gtb + pc * 16384 + tid * 64;
            uint32_t sa = smem_u32(sm + SM_TLN + pc * 16384 + tid * 64);
#pragma unroll
            for (int j = 0; j < 4; ++j)
                asm volatile("cp.async.cg.shared.global [%0], [%1], 16;"
                             :: "r"(sa + j * 16), "l"(gp + j * 16) : "memory");
            asm volatile("cp.async.commit_group;" ::: "memory");
        }

        float acc[6][4];
#pragma unroll
        for (int nf = 0; nf < 6; ++nf)
#pragma unroll
            for (int q = 0; q < 4; ++q) acc[nf][q] = 0.f;

        const int sbase = (tile & 1) * 128;

        for (int c = 0; c < 8; ++c) {
            if (c < 7) asm volatile("cp.async.wait_group 1;" ::: "memory");
            else       asm volatile("cp.async.wait_group 0;" ::: "memory");
            __syncthreads();
            if (c + 2 < 8) {
                int bi = (c + 2) % 3;
                const char* gp = gtb + (c + 2) * 16384 + tid * 64;
                uint32_t sa = smem_u32(sm + SM_TLN + bi * 16384 + tid * 64);
#pragma unroll
                for (int j = 0; j < 4; ++j)
                    asm volatile("cp.async.cg.shared.global [%0], [%1], 16;"
                                 :: "r"(sa + j * 16), "l"(gp + j * 16) : "memory");
                asm volatile("cp.async.commit_group;" ::: "memory");
            }

            const char* tb = sm + SM_TLN + (c % 3) * 16384;
#pragma unroll
            for (int sub = 0; sub < 4; ++sub) {
                const int kc = c * 4 + sub;
                const char* tsub = tb + sub * 4096;
                uint2 A0 = *(const uint2*)(tsub + u0 * 32 + tig * 8);
                uint2 A1 = *(const uint2*)(tsub + (u0 + 8) * 32 + tig * 8);
                uint2 S = srcp2[sbase + kc * 4 + tig];       // LDS.64 broadcast

                uint32_t a0 = tanh2(hadd2u(A0.x, S.x));
                uint32_t a2 = tanh2(hadd2u(A0.y, S.y));
                uint32_t a1 = tanh2(hadd2u(A1.x, S.x));
                uint32_t a3 = tanh2(hadd2u(A1.y, S.y));

                const uint4* bp = Bsv + (kc * 32 + lane) * 3;
                uint4 B0 = bp[0], B1 = bp[1], B2 = bp[2];
                mma16816(acc[0], a0, a1, a2, a3, B0.x, B0.y);
                mma16816(acc[1], a0, a1, a2, a3, B0.z, B0.w);
                mma16816(acc[2], a0, a1, a2, a3, B1.x, B1.y);
                mma16816(acc[3], a0, a1, a2, a3, B1.z, B1.w);
                mma16816(acc[4], a0, a1, a2, a3, B2.x, B2.y);
                mma16816(acc[5], a0, a1, a2, a3, B2.z, B2.w);
            }
        }

        // epilogue: stage in smem (tln buffers are free now), then coalesced stores
        float* stage = (float*)(sm + SM_TLN);
        {
            float* st0 = stage + u0 * Vd;
            float* st1 = stage + (u0 + 8) * Vd;
#pragma unroll
            for (int nf = 0; nf < 6; ++nf) {
                int n = nf * 8 + tig * 2;
                if (n < Vd) {
                    float bb0 = bls[n];
                    st0[n] = acc[nf][0] + bb0;
                    st1[n] = acc[nf][2] + bb0;
                }
                if (n + 1 < Vd) {
                    float bb1 = bls[n + 1];
                    st0[n + 1] = acc[nf][1] + bb1;
                    st1[n + 1] = acc[nf][3] + bb1;
                }
            }
        }
        __syncthreads();
        {
            float4* dst = (float4*)(out + (size_t)tile * (Ud * Vd));
            const float4* sg = (const float4*)stage;
            for (int i = tid; i < (Ud * Vd) / 4; i += 256) dst[i] = sg[i];
        }
    }
}

__global__ void k_tail(const int* __restrict__ sl, const int* __restrict__ tl,
                       float* __restrict__ out, long long base, int count) {
    int i = threadIdx.x;
    if (i < 4 && i < count) out[base + i] = (float)sl[i];
    else if (i >= 4 && i < 8 && i < count) out[base + i] = (float)tl[i - 4];
}

extern "C" void kernel_launch(void* const* d_in, const int* in_sizes, int n_in,
                              void* d_out, int out_size) {
    const float* src = (const float*)d_in[0];
    const int*   slen = (const int*)d_in[1];
    const float* tgt = (const float*)d_in[2];
    const int*   tlen = (const int*)d_in[3];
    const float* W1 = (const float*)d_in[4];
    const float* b1 = (const float*)d_in[5];
    const float* W2 = (const float*)d_in[6];
    const float* b2 = (const float*)d_in[7];
    const float* lng = (const float*)d_in[8];
    const float* lnb = (const float*)d_in[9];
    const float* Wl = (const float*)d_in[10];
    const float* bl = (const float*)d_in[11];
    float* out = (float*)d_out;

    cudaFuncSetAttribute(k_fused, cudaFuncAttributeMaxDynamicSharedMemorySize, SM_TOT);

    k_gemm1<<<Bd * Ud / 8, 256>>>(tgt, W1, b1);                  // idx 0
    k_prepB<<<48, 256>>>(Wl);                                    // idx 1
    k_gemm2_ln<<<Bd * Ud / 8, 256>>>(W2, b2, lng, lnb);          // idx 2
    k_fused<<<296, 256, SM_TOT>>>(src, bl, out);                 // idx 3  (ncu capture slot)

    const long long MAIN = (long long)Bd * Td * Ud * Vd;   // 10,747,904
    if ((long long)out_size > MAIN) {
        int extra = (int)((long long)out_size - MAIN);
        if (extra > 8) extra = 8;
        k_tail<<<1, 8>>>(slen, tlen, out, MAIN, extra);
    }
}

// round 8
// speedup vs baseline: 4.0924x; 1.3622x over previous
#include <cuda_runtime.h>
#include <cuda_fp16.h>
#include <cstdint>
#include <math.h>

#define Hd 512
#define Bd 4
#define Td 512
#define Ud 128
#define Vd 41
#define NTILES (Bd * Td)
#define NPAIRS (NTILES / 2)

// ---------------- scratch ----------------
__device__ float g_h1[Bd * Ud * Hd];                         // gelu(tgt@W1+b1)
__device__ __align__(256) __half g_tlnh[Bd * Ud * Hd];       // LN target fp16, [b][kc(32)][u(128)][perm16]
__device__ __align__(256) uint32_t g_Bfrag[3 * 32 * 32 * 4]; // Wl fp16 B-frags [part(3)][kc][lane][w4]

// ---------------- helpers ----------------
__device__ __forceinline__ uint32_t smem_u32(const void* p) {
    uint32_t a;
    asm("{ .reg .u64 t; cvta.to.shared.u64 t, %1; cvt.u32.u64 %0, t; }" : "=r"(a) : "l"(p));
    return a;
}
__device__ __forceinline__ uint32_t f2h(float x, float y) {
    __half2 h = __floats2half2_rn(x, y);
    return *reinterpret_cast<uint32_t*>(&h);
}
__device__ __forceinline__ uint32_t hadd2u(uint32_t a, uint32_t b) {
    uint32_t d;
    asm("add.f16x2 %0, %1, %2;" : "=r"(d) : "r"(a), "r"(b));
    return d;
}
__device__ __forceinline__ uint32_t tanh2(uint32_t x) {
    asm("tanh.approx.f16x2 %0, %0;" : "+r"(x));
    return x;
}
__device__ __forceinline__ void mma16816(float* c, uint32_t a0, uint32_t a1, uint32_t a2, uint32_t a3,
                                         uint32_t b0, uint32_t b1) {
    asm volatile(
        "mma.sync.aligned.m16n8k16.row.col.f32.f16.f16.f32 "
        "{%0,%1,%2,%3}, {%4,%5,%6,%7}, {%8,%9}, {%0,%1,%2,%3};"
        : "+f"(c[0]), "+f"(c[1]), "+f"(c[2]), "+f"(c[3])
        : "r"(a0), "r"(a1), "r"(a2), "r"(a3), "r"(b0), "r"(b1));
}

// packed f32x2 (prologue GEMMs)
__device__ __forceinline__ unsigned long long pack2(float x, float y) {
    unsigned long long r; asm("mov.b64 %0, {%1, %2};" : "=l"(r) : "f"(x), "f"(y)); return r;
}
__device__ __forceinline__ void unpack2(unsigned long long v, float& x, float& y) {
    asm("mov.b64 {%0, %1}, %2;" : "=f"(x), "=f"(y) : "l"(v));
}
__device__ __forceinline__ unsigned long long fma2(unsigned long long a, unsigned long long b, unsigned long long c) {
    unsigned long long d; asm("fma.rn.f32x2 %0, %1, %2, %3;" : "=l"(d) : "l"(a), "l"(b), "l"(c)); return d;
}

// =====================================================================
// Kernel 1a: h1 = gelu(tgt @ W1 + b1). 128 blocks = 64 row-tiles x 2 col-halves.
// =====================================================================
__global__ __launch_bounds__(128) void k_gemm1(const float* __restrict__ tgt,
                                               const float* __restrict__ W1,
                                               const float* __restrict__ b1) {
    __shared__ unsigned long long As2[8][Hd];
    const int m0 = (blockIdx.x >> 1) * 8;
    const int ch = blockIdx.x & 1;
    const int tid = threadIdx.x;

    for (int i = tid; i < 8 * Hd; i += 128) {
        float v = tgt[m0 * Hd + i];
        ((unsigned long long*)As2)[i] = pack2(v, v);
    }
    __syncthreads();

    const int j0 = ch * 256 + tid * 2;
    unsigned long long acc[8];
    {
        unsigned long long bb = pack2(b1[j0], b1[j0 + 1]);
#pragma unroll
        for (int r = 0; r < 8; r++) acc[r] = bb;
    }
    for (int k = 0; k < Hd; k += 4) {
        unsigned long long w[4];
#pragma unroll
        for (int q = 0; q < 4; q++) {
            float2 wv = *(const float2*)(W1 + (k + q) * Hd + j0);
            w[q] = pack2(wv.x, wv.y);
        }
#pragma unroll
        for (int q = 0; q < 4; q++)
#pragma unroll
            for (int r = 0; r < 8; r++) acc[r] = fma2(As2[r][k + q], w[q], acc[r]);
    }
#pragma unroll
    for (int r = 0; r < 8; r++) {
        float x, y; unpack2(acc[r], x, y);
        float gx = 0.5f * x * (1.0f + erff(x * 0.7071067811865475f));
        float gy = 0.5f * y * (1.0f + erff(y * 0.7071067811865475f));
        *(float2*)(g_h1 + (m0 + r) * Hd + j0) = make_float2(gx, gy);
    }
}

// =====================================================================
// Kernel 1b: h2 = h1 @ W2 + b2; layernorm; store fp16 permuted.
// 128 blocks x 4 rows, 256 threads.
// layout: g_tlnh[((b*32+kc)*128+u)*16 + tig*4 + hi*2 + lo], k = kc*16+tig*2+hi*8+lo
// =====================================================================
__global__ __launch_bounds__(256) void k_gemm2_ln(const float* __restrict__ W2,
                                                  const float* __restrict__ b2,
                                                  const float* __restrict__ lng,
                                                  const float* __restrict__ lnb) {
    __shared__ unsigned long long As2[4][Hd];
    __shared__ float redS[4][8], redQ[4][8];
    __shared__ float mu_s[4], rs_s[4];
    const int m0 = blockIdx.x * 4;
    const int tid = threadIdx.x;
    const int w = tid >> 5, lane = tid & 31;

    for (int i = tid; i < 4 * Hd; i += 256) {
        float v = g_h1[m0 * Hd + i];
        ((unsigned long long*)As2)[i] = pack2(v, v);
    }
    __syncthreads();

    const int j0 = tid * 2;
    unsigned long long acc[4];
    {
        unsigned long long bb = pack2(b2[j0], b2[j0 + 1]);
#pragma unroll
        for (int r = 0; r < 4; r++) acc[r] = bb;
    }
    for (int k = 0; k < Hd; k += 4) {
        unsigned long long wv4[4];
#pragma unroll
        for (int q = 0; q < 4; q++) {
            float2 wv = *(const float2*)(W2 + (k + q) * Hd + j0);
            wv4[q] = pack2(wv.x, wv.y);
        }
#pragma unroll
        for (int q = 0; q < 4; q++)
#pragma unroll
            for (int r = 0; r < 4; r++) acc[r] = fma2(As2[r][k + q], wv4[q], acc[r]);
    }

    float xs[4], ys[4];
#pragma unroll
    for (int r = 0; r < 4; r++) unpack2(acc[r], xs[r], ys[r]);

#pragma unroll
    for (int r = 0; r < 4; r++) {
        float s = xs[r] + ys[r];
        float q = xs[r] * xs[r] + ys[r] * ys[r];
#pragma unroll
        for (int off = 16; off > 0; off >>= 1) {
            s += __shfl_down_sync(0xFFFFFFFFu, s, off);
            q += __shfl_down_sync(0xFFFFFFFFu, q, off);
        }
        if (lane == 0) { redS[r][w] = s; redQ[r][w] = q; }
    }
    __syncthreads();
    if (tid < 4) {
        float s = 0.f, q = 0.f;
#pragma unroll
        for (int j = 0; j < 8; j++) { s += redS[tid][j]; q += redQ[tid][j]; }
        float mu = s * (1.0f / Hd);
        float var = q * (1.0f / Hd) - mu * mu;
        mu_s[tid] = mu;
        rs_s[tid] = rsqrtf(var + 1e-5f);
    }
    __syncthreads();

    const float gx = lng[j0], gy = lng[j0 + 1];
    const float bx = lnb[j0], by = lnb[j0 + 1];
    const int kc = j0 >> 4, tig = (j0 >> 1) & 3, hi = (j0 >> 3) & 1;
#pragma unroll
    for (int r = 0; r < 4; r++) {
        int m = m0 + r;
        int bb = m >> 7, u = m & 127;
        float ox = (xs[r] - mu_s[r]) * rs_s[r] * gx + bx;
        float oy = (ys[r] - mu_s[r]) * rs_s[r] * gy + by;
        __half2 hv = __floats2half2_rn(ox, oy);
        *(__half2*)(g_tlnh + (((size_t)(bb * 32 + kc) * 128 + u) * 16 + tig * 4 + hi * 2)) = hv;
    }
}

// =====================================================================
// prepB: Wl -> fp16 B-frags in conflict-free layout [part(3)][kc][lane][w]
// word w: nf = part*2 + (w>>1), r = w&1
// value = half2(Wl[k0][n], Wl[k0+1][n]), k0 = kc*16+tig*2+r*8, n = nf*8+gid
// =====================================================================
__global__ void k_prepB(const float* __restrict__ Wl) {
    int idx = blockIdx.x * 256 + threadIdx.x;   // 0..12287
    if (idx >= 12288) return;
    int part = idx >> 12;
    int rem = idx & 4095;
    int kc = rem >> 7;
    int lane = (rem >> 2) & 31;
    int wd = idx & 3;
    int nf = part * 2 + (wd >> 1);
    int r = wd & 1;
    int gid = lane >> 2, tig = lane & 3;
    int n = nf * 8 + gid;
    int k0 = kc * 16 + tig * 2 + r * 8;
    float lo = (n < Vd) ? Wl[k0 * Vd + n] : 0.f;
    float hi = (n < Vd) ? Wl[(k0 + 1) * Vd + n] : 0.f;
    g_Bfrag[idx] = f2h(lo, hi);
}

// =====================================================================
// Fused: tile-pair per block. act = tanh2(srch + tln) -> mma -> staged epilogue
// =====================================================================
#define SM_BS   0          // 48KB B frags (3 conflict-free 16KB arrays)
#define SM_TLN  49152      // 3 x 16KB tln chunk buffers; reused as 42KB epilogue stage
#define SM_SRCP 98304      // 2 par x 32 kc x 4 tig x uint4 = 4KB
#define SM_BLS  102400
#define SM_TOT  102656

__global__ __launch_bounds__(256, 2)
void k_fused(const float* __restrict__ src, const float* __restrict__ bl,
             float* __restrict__ out) {
    extern __shared__ __align__(16) char sm[];
    const int tid = threadIdx.x, w = tid >> 5, lane = tid & 31;
    const int gid = lane >> 2, tig = lane & 3;

    // one-time: copy B fragments (48KB) + padded bias
    {
        uint4* Bs = (uint4*)(sm + SM_BS);
        const uint4* Bg = (const uint4*)g_Bfrag;
        for (int i = tid; i < 3072; i += 256) Bs[i] = Bg[i];
        float* bls = (float*)(sm + SM_BLS);
        if (tid < 48) bls[tid] = (tid < Vd) ? bl[tid] : 0.f;
    }

    const uint4* Bsv = (const uint4*)(sm + SM_BS);
    const uint4* srcp4 = (const uint4*)(sm + SM_SRCP);
    const float* bls = (const float*)(sm + SM_BLS);
    const int u0 = w * 16 + gid;

    int par = 0;
    for (int pair = blockIdx.x; pair < NPAIRS; pair += gridDim.x) {
        const int tile0 = pair * 2;
        const int b = tile0 >> 9;
        __syncthreads();   // previous epilogue reads + srcp reads done

        // stage both tiles' src rows as packed half2 quads
        if (tid < 128) {
            int kc = tid >> 2, tg = tid & 3;
            const float* s0 = src + (size_t)tile0 * Hd + kc * 16 + tg * 2;
            float2 xa0 = *(const float2*)(s0);
            float2 xb0 = *(const float2*)(s0 + 8);
            float2 xa1 = *(const float2*)(s0 + Hd);
            float2 xb1 = *(const float2*)(s0 + Hd + 8);
            uint4 pv;
            pv.x = f2h(xa0.x, xa0.y);
            pv.y = f2h(xb0.x, xb0.y);
            pv.z = f2h(xa1.x, xa1.y);
            pv.w = f2h(xb1.x, xb1.y);
            ((uint4*)(sm + SM_SRCP))[par * 128 + tid] = pv;
        }

        // prefetch tln K64-chunks 0,1 (triple-buffered cp.async)
        const char* gtb = (const char*)g_tlnh + (size_t)b * 131072;
#pragma unroll
        for (int pc = 0; pc < 2; ++pc) {
            const char* gp = gtb + pc * 16384 + tid * 64;
            uint32_t sa = smem_u32(sm + SM_TLN + pc * 16384 + tid * 64);
#pragma unroll
            for (int j = 0; j < 4; ++j)
                asm volatile("cp.async.cg.shared.global [%0], [%1], 16;"
                             :: "r"(sa + j * 16), "l"(gp + j * 16) : "memory");
            asm volatile("cp.async.commit_group;" ::: "memory");
        }

        float acc0[6][4], acc1[6][4];
#pragma unroll
        for (int nf = 0; nf < 6; ++nf)
#pragma unroll
            for (int q = 0; q < 4; ++q) { acc0[nf][q] = 0.f; acc1[nf][q] = 0.f; }

        const int sbase = par * 128;

        for (int c = 0; c < 8; ++c) {
            if (c < 7) asm volatile("cp.async.wait_group 1;" ::: "memory");
            else       asm volatile("cp.async.wait_group 0;" ::: "memory");
            __syncthreads();
            if (c + 2 < 8) {
                int bi = (c + 2) % 3;
                const char* gp = gtb + (c + 2) * 16384 + tid * 64;
                uint32_t sa = smem_u32(sm + SM_TLN + bi * 16384 + tid * 64);
#pragma unroll
                for (int j = 0; j < 4; ++j)
                    asm volatile("cp.async.cg.shared.global [%0], [%1], 16;"
                                 :: "r"(sa + j * 16), "l"(gp + j * 16) : "memory");
                asm volatile("cp.async.commit_group;" ::: "memory");
            }

            const char* tb = sm + SM_TLN + (c % 3) * 16384;
#pragma unroll
            for (int sub = 0; sub < 4; ++sub) {
                const int kc = c * 4 + sub;
                const char* tsub = tb + sub * 4096;
                uint2 A0 = *(const uint2*)(tsub + u0 * 32 + tig * 8);
                uint2 A1 = *(const uint2*)(tsub + (u0 + 8) * 32 + tig * 8);
                uint4 Sv = srcp4[sbase + kc * 4 + tig];      // LDS.128, 4 distinct addrs

                uint32_t a0 = tanh2(hadd2u(A0.x, Sv.x));
                uint32_t a2 = tanh2(hadd2u(A0.y, Sv.y));
                uint32_t a1 = tanh2(hadd2u(A1.x, Sv.x));
                uint32_t a3 = tanh2(hadd2u(A1.y, Sv.y));
                uint32_t c0 = tanh2(hadd2u(A0.x, Sv.z));
                uint32_t c2 = tanh2(hadd2u(A0.y, Sv.w));
                uint32_t c1 = tanh2(hadd2u(A1.x, Sv.z));
                uint32_t c3 = tanh2(hadd2u(A1.y, Sv.w));

                const uint4* bp = Bsv + kc * 32 + lane;      // lane-stride 16B: conflict-free
                uint4 B0 = bp[0];
                uint4 B1 = bp[1024];
                uint4 B2 = bp[2048];
                mma16816(acc0[0], a0, a1, a2, a3, B0.x, B0.y);
                mma16816(acc1[0], c0, c1, c2, c3, B0.x, B0.y);
                mma16816(acc0[1], a0, a1, a2, a3, B0.z, B0.w);
                mma16816(acc1[1], c0, c1, c2, c3, B0.z, B0.w);
                mma16816(acc0[2], a0, a1, a2, a3, B1.x, B1.y);
                mma16816(acc1[2], c0, c1, c2, c3, B1.x, B1.y);
                mma16816(acc0[3], a0, a1, a2, a3, B1.z, B1.w);
                mma16816(acc1[3], c0, c1, c2, c3, B1.z, B1.w);
                mma16816(acc0[4], a0, a1, a2, a3, B2.x, B2.y);
                mma16816(acc1[4], c0, c1, c2, c3, B2.x, B2.y);
                mma16816(acc0[5], a0, a1, a2, a3, B2.z, B2.w);
                mma16816(acc1[5], c0, c1, c2, c3, B2.z, B2.w);
            }
        }

        // epilogue: stage both tiles (42KB in tln area), then coalesced stores
        __syncthreads();   // all warps done reading A chunks
        float* stage = (float*)(sm + SM_TLN);
        {
            float* s00 = stage + u0 * Vd;
            float* s01 = stage + (u0 + 8) * Vd;
            float* s10 = stage + (128 + u0) * Vd;
            float* s11 = stage + (128 + u0 + 8) * Vd;
#pragma unroll
            for (int nf = 0; nf < 6; ++nf) {
                int n = nf * 8 + tig * 2;
                if (n < Vd) {
                    float bb0 = bls[n];
                    s00[n] = acc0[nf][0] + bb0;
                    s01[n] = acc0[nf][2] + bb0;
                    s10[n] = acc1[nf][0] + bb0;
                    s11[n] = acc1[nf][2] + bb0;
                }
                if (n + 1 < Vd) {
                    float bb1 = bls[n + 1];
                    s00[n + 1] = acc0[nf][1] + bb1;
                    s01[n + 1] = acc0[nf][3] + bb1;
                    s10[n + 1] = acc1[nf][1] + bb1;
                    s11[n + 1] = acc1[nf][3] + bb1;
                }
            }
        }
        __syncthreads();
        {
            float4* dst = (float4*)(out + (size_t)tile0 * (Ud * Vd));
            const float4* sg = (const float4*)stage;
            for (int i = tid; i < (2 * Ud * Vd) / 4; i += 256) dst[i] = sg[i];
        }
        par ^= 1;
    }
}

__global__ void k_tail(const int* __restrict__ sl, const int* __restrict__ tl,
                       float* __restrict__ out, long long base, int count) {
    int i = threadIdx.x;
    if (i < 4 && i < count) out[base + i] = (float)sl[i];
    else if (i >= 4 && i < 8 && i < count) out[base + i] = (float)tl[i - 4];
}

extern "C" void kernel_launch(void* const* d_in, const int* in_sizes, int n_in,
                              void* d_out, int out_size) {
    const float* src = (const float*)d_in[0];
    const int*   slen = (const int*)d_in[1];
    const float* tgt = (const float*)d_in[2];
    const int*   tlen = (const int*)d_in[3];
    const float* W1 = (const float*)d_in[4];
    const float* b1 = (const float*)d_in[5];
    const float* W2 = (const float*)d_in[6];
    const float* b2 = (const float*)d_in[7];
    const float* lng = (const float*)d_in[8];
    const float* lnb = (const float*)d_in[9];
    const float* Wl = (const float*)d_in[10];
    const float* bl = (const float*)d_in[11];
    float* out = (float*)d_out;

    cudaFuncSetAttribute(k_fused, cudaFuncAttributeMaxDynamicSharedMemorySize, SM_TOT);

    k_gemm1<<<128, 128>>>(tgt, W1, b1);                          // idx 0
    k_prepB<<<48, 256>>>(Wl);                                    // idx 1
    k_gemm2_ln<<<128, 256>>>(W2, b2, lng, lnb);                  // idx 2
    k_fused<<<296, 256, SM_TOT>>>(src, bl, out);                 // idx 3  (ncu capture slot)

    const long long MAIN = (long long)Bd * Td * Ud * Vd;   // 10,747,904
    if ((long long)out_size > MAIN) {
        int extra = (int)((long long)out_size - MAIN);
        if (extra > 8) extra = 8;
        k_tail<<<1, 8>>>(slen, tlen, out, MAIN, extra);
    }
}